// round 3
// baseline (speedup 1.0000x reference)
#include <cuda_runtime.h>
#include <math.h>

#define Bsz 512
#define HH 84
#define WW 84
#define KOBJ 20
#define DEPTH 24
#define EMB 512

// ---------------- scratch (static device globals; no allocations) ----------------
__device__ float g_h1[Bsz * 32 * 20 * 20];          // conv1 out
__device__ float g_h2[Bsz * 64 * 9 * 9];            // conv2 out
__device__ float g_h3[Bsz * 64 * 7 * 7];            // conv3 out / feat
__device__ float g_x [Bsz * EMB];                   // fc out
__device__ float g_ot[Bsz * KOBJ * 2];
__device__ float g_ct[Bsz * 2];
__device__ float g_m21 [Bsz * DEPTH * 21 * 21];
__device__ float g_m42a[Bsz * DEPTH * 42 * 42];
__device__ float g_m42b[Bsz * DEPTH * 42 * 42];
__device__ float g_m84a[Bsz * DEPTH * 84 * 84];
__device__ float g_m84b[Bsz * DEPTH * 84 * 84];

// ---------------- conv1: [B,2,84,84] k8 s4 -> [B,32,20,20], relu ----------------
__global__ __launch_bounds__(256) void k_conv1(const float* __restrict__ inp,
                                               const float* __restrict__ w,
                                               const float* __restrict__ bias) {
    extern __shared__ float sm[];
    float* sIn = sm;          // 2*84*84 = 14112
    float* sW  = sm + 14112;  // 32*2*8*8 = 4096
    int b = blockIdx.x, tid = threadIdx.x;
    const float* ip = inp + b * 14112;
    for (int i = tid; i < 14112; i += 256) sIn[i] = ip[i];
    for (int i = tid; i < 4096;  i += 256) sW[i]  = w[i];
    __syncthreads();
    // each item = 2x2 output block: 32 oc * 10 * 10 = 3200 items
    for (int o = tid; o < 3200; o += 256) {
        int oc = o / 100; int r = o % 100;
        int oy = (r / 10) * 2, ox = (r % 10) * 2;
        float a00 = 0.f, a01 = 0.f, a10 = 0.f, a11 = 0.f;
        for (int ic = 0; ic < 2; ic++) {
            const float* wp  = sW + (oc * 2 + ic) * 64;
            const float* inb = sIn + ic * 7056;
            #pragma unroll
            for (int ky = 0; ky < 8; ky++) {
                const float* r0 = inb + (oy * 4 + ky) * 84 + ox * 4;
                const float* r1 = r0 + 4 * 84;
                float v0[12], v1[12];
                #pragma unroll
                for (int j = 0; j < 12; j++) { v0[j] = r0[j]; v1[j] = r1[j]; }
                #pragma unroll
                for (int kx = 0; kx < 8; kx++) {
                    float ww = wp[ky * 8 + kx];
                    a00 += v0[kx] * ww;  a01 += v0[kx + 4] * ww;
                    a10 += v1[kx] * ww;  a11 += v1[kx + 4] * ww;
                }
            }
        }
        float bb = bias[oc];
        float* op = g_h1 + b * 12800 + oc * 400 + oy * 20 + ox;
        op[0]  = fmaxf(a00 + bb, 0.f); op[1]  = fmaxf(a01 + bb, 0.f);
        op[20] = fmaxf(a10 + bb, 0.f); op[21] = fmaxf(a11 + bb, 0.f);
    }
}

// ---------------- conv2: [B,32,20,20] k4 s2 -> [B,64,9,9], relu ----------------
__global__ __launch_bounds__(256) void k_conv2(const float* __restrict__ w,
                                               const float* __restrict__ bias) {
    extern __shared__ float sm[];
    float* sIn = sm;          // 32*20*20 = 12800
    float* sW  = sm + 12800;  // chunk: 32 oc * 32 ic * 16 = 16384
    int b = blockIdx.x, tid = threadIdx.x;
    const float* ip = g_h1 + b * 12800;
    for (int i = tid; i < 12800; i += 256) sIn[i] = ip[i];
    for (int ch = 0; ch < 2; ch++) {
        __syncthreads();
        for (int i = tid; i < 16384; i += 256) sW[i] = w[ch * 16384 + i];
        __syncthreads();
        // items: 8 oc-groups(of 4) x 9 oy x 3 ox-triples = 216
        if (tid < 216) {
            int ocg = tid / 27; int r = tid % 27; int oy = r / 3; int oxg = (r % 3) * 3;
            float acc[4][3] = {};
            int iy0 = oy * 2, ix0 = oxg * 2;
            for (int ic = 0; ic < 32; ic++) {
                #pragma unroll
                for (int ky = 0; ky < 4; ky++) {
                    const float* rp = sIn + ic * 400 + (iy0 + ky) * 20 + ix0;
                    float v[8];
                    #pragma unroll
                    for (int j = 0; j < 8; j++) v[j] = rp[j];
                    #pragma unroll
                    for (int u = 0; u < 4; u++) {
                        const float* wp = sW + ((ocg * 4 + u) * 32 + ic) * 16 + ky * 4;
                        #pragma unroll
                        for (int kx = 0; kx < 4; kx++) {
                            float ww = wp[kx];
                            acc[u][0] += v[kx] * ww;
                            acc[u][1] += v[kx + 2] * ww;
                            acc[u][2] += v[kx + 4] * ww;
                        }
                    }
                }
            }
            #pragma unroll
            for (int u = 0; u < 4; u++) {
                int oc = ch * 32 + ocg * 4 + u;
                float bb = bias[oc];
                float* op = g_h2 + b * 5184 + oc * 81 + oy * 9 + oxg;
                #pragma unroll
                for (int j = 0; j < 3; j++) op[j] = fmaxf(acc[u][j] + bb, 0.f);
            }
        }
    }
}

// ---------------- conv3: [B,64,9,9] k3 s1 -> [B,64,7,7], relu ----------------
__global__ __launch_bounds__(256) void k_conv3(const float* __restrict__ w,
                                               const float* __restrict__ bias) {
    extern __shared__ float sm[];
    float* sIn = sm;         // 64*81 = 5184
    float* sW  = sm + 5184;  // 64*64*9 = 36864
    int b = blockIdx.x, tid = threadIdx.x;
    const float* ip = g_h2 + b * 5184;
    for (int i = tid; i < 5184;  i += 256) sIn[i] = ip[i];
    for (int i = tid; i < 36864; i += 256) sW[i]  = w[i];
    __syncthreads();
    // items: 64 oc x 7 oy = 448; each does a full row of 7
    for (int it = tid; it < 448; it += 256) {
        int oc = it / 7, oy = it % 7;
        float acc[7] = {};
        for (int ic = 0; ic < 64; ic++) {
            const float* wp = sW + (oc * 64 + ic) * 9;
            #pragma unroll
            for (int ky = 0; ky < 3; ky++) {
                const float* rp = sIn + ic * 81 + (oy + ky) * 9;
                float v[9];
                #pragma unroll
                for (int j = 0; j < 9; j++) v[j] = rp[j];
                #pragma unroll
                for (int kx = 0; kx < 3; kx++) {
                    float ww = wp[ky * 3 + kx];
                    #pragma unroll
                    for (int j = 0; j < 7; j++) acc[j] += v[j + kx] * ww;
                }
            }
        }
        float bb = bias[oc];
        float* op = g_h3 + b * 3136 + oc * 49 + oy * 7;
        #pragma unroll
        for (int j = 0; j < 7; j++) op[j] = fmaxf(acc[j] + bb, 0.f);
    }
}

// ---------------- generic GEMM: C[M,N] = act(A[M,K] * W[N,K]^T + bias) ----------------
#define BM 64
#define BN 64
#define BK 16
__global__ __launch_bounds__(256) void k_gemm(const float* __restrict__ A,
                                              const float* __restrict__ W,
                                              const float* __restrict__ bias,
                                              float* __restrict__ C,
                                              int M, int N, int K, int relu) {
    __shared__ float As[BK][BM + 1];
    __shared__ float Ws[BK][BN + 1];
    int bm = blockIdx.y * BM, bn = blockIdx.x * BN;
    int tid = threadIdx.x;
    float acc[4][4] = {};
    for (int k0 = 0; k0 < K; k0 += BK) {
        for (int i = tid; i < BM * BK; i += 256) {
            int m = i / BK, k = i % BK;
            int gm = bm + m, gk = k0 + k;
            As[k][m] = (gm < M && gk < K) ? A[gm * K + gk] : 0.f;
        }
        for (int i = tid; i < BN * BK; i += 256) {
            int n = i / BK, k = i % BK;
            int gn = bn + n, gk = k0 + k;
            Ws[k][n] = (gn < N && gk < K) ? W[gn * K + gk] : 0.f;
        }
        __syncthreads();
        int tm = (tid / 16) * 4, tn = (tid % 16) * 4;
        #pragma unroll
        for (int k = 0; k < BK; k++) {
            float a[4], bb[4];
            #pragma unroll
            for (int i = 0; i < 4; i++) a[i] = As[k][tm + i];
            #pragma unroll
            for (int j = 0; j < 4; j++) bb[j] = Ws[k][tn + j];
            #pragma unroll
            for (int i = 0; i < 4; i++)
                #pragma unroll
                for (int j = 0; j < 4; j++) acc[i][j] += a[i] * bb[j];
        }
        __syncthreads();
    }
    int tm = bm + (tid / 16) * 4, tn = bn + (tid % 16) * 4;
    #pragma unroll
    for (int i = 0; i < 4; i++)
        #pragma unroll
        for (int j = 0; j < 4; j++) {
            int m = tm + i, n = tn + j;
            if (m < M && n < N) {
                float v = acc[i][j] + bias[n];
                if (relu) v = fmaxf(v, 0.f);
                C[m * N + n] = v;
            }
        }
}

// ---------------- heads: ot[B,40], ct[B,2] ----------------
__global__ __launch_bounds__(64) void k_heads(const float* __restrict__ otw,
                                              const float* __restrict__ otb,
                                              const float* __restrict__ ctw,
                                              const float* __restrict__ ctb) {
    __shared__ float sx[EMB];
    int b = blockIdx.x, tid = threadIdx.x;
    for (int i = tid; i < EMB; i += 64) sx[i] = g_x[b * EMB + i];
    __syncthreads();
    if (tid < 42) {
        const float* wp = (tid < 40) ? (otw + tid * EMB) : (ctw + (tid - 40) * EMB);
        float s = (tid < 40) ? otb[tid] : ctb[tid - 40];
        for (int k = 0; k < EMB; k++) s += sx[k] * wp[k];
        if (tid < 40) g_ot[b * 40 + tid] = s;
        else          g_ct[b * 2 + (tid - 40)] = s;
    }
}

// ---------------- bilinear upsample (align_corners) ----------------
__global__ __launch_bounds__(256) void k_upsample(const float* __restrict__ in,
                                                  float* __restrict__ out,
                                                  int inS, int outS, int total) {
    int idx = blockIdx.x * blockDim.x + threadIdx.x;
    if (idx >= total) return;
    int X = idx % outS; int t = idx / outS; int Y = t % outS; int bc = t / outS;
    float scale = (float)(inS - 1) / (float)(outS - 1);
    float py = Y * scale, px = X * scale;
    int y0 = min((int)py, inS - 2);
    int x0 = min((int)px, inS - 2);
    float wy = py - (float)y0, wx = px - (float)x0;
    const float* p = in + (bc * inS + y0) * inS + x0;
    float v00 = p[0], v01 = p[1], v10 = p[inS], v11 = p[inS + 1];
    out[idx] = (1.f - wy) * ((1.f - wx) * v00 + wx * v01) +
               wy * ((1.f - wx) * v10 + wx * v11);
}

// ---------------- residual 3x3 conv (24ch, pad 1): out = relu(in + conv(in) + b) ----------------
// tile = TH=6 full-width rows; each thread: 2 x-positions * 24 oc accumulators
__global__ __launch_bounds__(256) void k_convres(const float* __restrict__ in,
                                                 const float* __restrict__ w,
                                                 const float* __restrict__ bias,
                                                 float* __restrict__ out, int S) {
    extern __shared__ float sm[];
    const int TH = 6;
    int Sp = S + 2;
    float* sIn = sm;                       // 24*(TH+2)*Sp
    float* sW  = sm + 24 * (TH + 2) * Sp;  // 24*24*9 = 5184
    int b = blockIdx.y, ty = blockIdx.x;
    int tid = threadIdx.x, nt = blockDim.x;
    int y0 = ty * TH;
    const float* ip = in + b * 24 * S * S;
    int tileElems = 24 * (TH + 2) * Sp;
    for (int i = tid; i < tileElems; i += nt) {
        int cx = i % Sp; int t = i / Sp; int ry = t % (TH + 2); int c = t / (TH + 2);
        int gy = y0 + ry - 1, gx = cx - 1;
        float v = 0.f;
        if (gy >= 0 && gy < S && gx >= 0 && gx < S) v = ip[(c * S + gy) * S + gx];
        sIn[i] = v;
    }
    for (int i = tid; i < 5184; i += nt) sW[i] = w[i];
    __syncthreads();
    int npairs = (S / 2) * TH;
    if (tid < npairs) {
        int py = tid / (S / 2);
        int px = (tid % (S / 2)) * 2;
        float acc0[24], acc1[24];
        #pragma unroll
        for (int o = 0; o < 24; o++) { acc0[o] = 0.f; acc1[o] = 0.f; }
        for (int ic = 0; ic < 24; ic++) {
            #pragma unroll
            for (int ky = 0; ky < 3; ky++) {
                const float* rp = sIn + (ic * (TH + 2) + py + ky) * Sp + px;
                float v0 = rp[0], v1 = rp[1], v2 = rp[2], v3 = rp[3];
                const float* wp = sW + ic * 9 + ky * 3;  // + oc*216
                #pragma unroll
                for (int oc = 0; oc < 24; oc++) {
                    float w0 = wp[oc * 216 + 0], w1 = wp[oc * 216 + 1], w2 = wp[oc * 216 + 2];
                    acc0[oc] += v0 * w0 + v1 * w1 + v2 * w2;
                    acc1[oc] += v1 * w0 + v2 * w1 + v3 * w2;
                }
            }
        }
        float* op = out + b * 24 * S * S;
        int gy = y0 + py;
        #pragma unroll
        for (int oc = 0; oc < 24; oc++) {
            float r0 = sIn[(oc * (TH + 2) + py + 1) * Sp + px + 1];
            float r1 = sIn[(oc * (TH + 2) + py + 1) * Sp + px + 2];
            float bb = bias[oc];
            op[(oc * S + gy) * S + px]     = fmaxf(acc0[oc] + r0 + bb, 0.f);
            op[(oc * S + gy) * S + px + 1] = fmaxf(acc1[oc] + r1 + bb, 0.f);
        }
    }
}

// ---------------- fused epilogue: 1x1 conv + sigmoid + flow + ct + grid + warp ----------------
__global__ __launch_bounds__(256) void k_final(const float* __restrict__ inp,
                                               const float* __restrict__ c3w,
                                               const float* __restrict__ c3b,
                                               float* __restrict__ outp) {
    __shared__ float s_w[KOBJ * 24];
    __shared__ float s_b[KOBJ];
    __shared__ float s_ot[KOBJ * 2];
    __shared__ float s_ct[2];
    int b = blockIdx.y, tid = threadIdx.x;
    int p = blockIdx.x * 256 + tid;
    for (int i = tid; i < KOBJ * 24; i += 256) s_w[i] = c3w[i];
    if (tid < KOBJ) s_b[tid] = c3b[tid];
    if (tid < KOBJ * 2) s_ot[tid] = g_ot[b * 40 + tid];
    if (tid < 2) s_ct[tid] = g_ct[b * 2 + tid];
    __syncthreads();
    if (p >= 7056) return;
    const float* mp = g_m84b + b * 24 * 7056 + p;
    float mv[24];
    #pragma unroll
    for (int c = 0; c < 24; c++) mv[c] = mp[c * 7056];
    float fy = s_ct[0], fx = s_ct[1];
    #pragma unroll 4
    for (int k = 0; k < KOBJ; k++) {
        float s = s_b[k];
        #pragma unroll
        for (int c = 0; c < 24; c++) s += mv[c] * s_w[k * 24 + c];
        float mask = 1.f / (1.f + __expf(-s));
        fy += mask * s_ot[k * 2];
        fx += mask * s_ot[k * 2 + 1];
    }
    int gy = p / 84, gx = p % 84;
    const float isf = 0.01f * 84.0f;
    float ys = isf * fy + (float)gy;
    float xs = isf * fx + (float)gx;
    const float* src = inp + b * 14112 + 7056;  // frame 1
    int x0 = min(max((int)floorf(xs), 0), 83);
    int y0 = min(max((int)floorf(ys), 0), 83);
    int x1 = min(x0 + 1, 83);
    int y1 = min(y0 + 1, 83);
    float Ia = src[y0 * 84 + x0], Ib = src[y1 * 84 + x0];
    float Ic = src[y0 * 84 + x1], Id = src[y1 * 84 + x1];
    float xc = fminf(fmaxf(xs, 0.f), 83.f);
    float yc = fminf(fmaxf(ys, 0.f), 83.f);
    float x0f = (float)x0, x1f = (float)x1, y0f = (float)y0, y1f = (float)y1;
    float o = (x1f - xc) * (y1f - yc) * Ia + (x1f - xc) * (yc - y0f) * Ib +
              (xc - x0f) * (y1f - yc) * Ic + (xc - x0f) * (yc - y0f) * Id;
    outp[b * 7056 + p] = o;
}

// ---------------- launch ----------------
extern "C" void kernel_launch(void* const* d_in, const int* in_sizes, int n_in,
                              void* d_out, int out_size) {
    const float* inp = (const float*)d_in[0];
    const float* cw1 = (const float*)d_in[1];
    const float* cb1 = (const float*)d_in[2];
    const float* cw2 = (const float*)d_in[3];
    const float* cb2 = (const float*)d_in[4];
    const float* cw3 = (const float*)d_in[5];
    const float* cb3 = (const float*)d_in[6];
    const float* fcw = (const float*)d_in[7];
    const float* fcb = (const float*)d_in[8];
    const float* otw = (const float*)d_in[9];
    const float* otb = (const float*)d_in[10];
    const float* ctw = (const float*)d_in[11];
    const float* ctb = (const float*)d_in[12];
    const float* m1w = (const float*)d_in[13];
    const float* m1b = (const float*)d_in[14];
    const float* c1w = (const float*)d_in[15];
    const float* c1b = (const float*)d_in[16];
    const float* c2w = (const float*)d_in[17];
    const float* c2b = (const float*)d_in[18];
    const float* c3w = (const float*)d_in[19];
    const float* c3b = (const float*)d_in[20];
    float* outp = (float*)d_out;

    // dynamic smem opt-in (>48KB); idempotent, capture-safe
    cudaFuncSetAttribute(k_conv1,  cudaFuncAttributeMaxDynamicSharedMemorySize, 72832);
    cudaFuncSetAttribute(k_conv2,  cudaFuncAttributeMaxDynamicSharedMemorySize, 116736);
    cudaFuncSetAttribute(k_conv3,  cudaFuncAttributeMaxDynamicSharedMemorySize, 168192);
    cudaFuncSetAttribute(k_convres, cudaFuncAttributeMaxDynamicSharedMemorySize, 86784);

    float *p_h3, *p_x, *p_m21, *p_m42a, *p_m42b, *p_m84a, *p_m84b;
    cudaGetSymbolAddress((void**)&p_h3,   g_h3);
    cudaGetSymbolAddress((void**)&p_x,    g_x);
    cudaGetSymbolAddress((void**)&p_m21,  g_m21);
    cudaGetSymbolAddress((void**)&p_m42a, g_m42a);
    cudaGetSymbolAddress((void**)&p_m42b, g_m42b);
    cudaGetSymbolAddress((void**)&p_m84a, g_m84a);
    cudaGetSymbolAddress((void**)&p_m84b, g_m84b);

    // encoder
    k_conv1<<<Bsz, 256, 72832>>>(inp, cw1, cb1);
    k_conv2<<<Bsz, 256, 116736>>>(cw2, cb2);
    k_conv3<<<Bsz, 256, 168192>>>(cw3, cb3);
    // fc: [512,3136] x [512,3136]^T -> [512,512], relu
    k_gemm<<<dim3(8, 8), 256>>>(p_h3, fcw, fcb, p_x, Bsz, EMB, 3136, 1);
    // mask fc: [512,512] x [10584,512]^T -> [512,10584]
    k_gemm<<<dim3((10584 + BN - 1) / BN, Bsz / BM), 256>>>(p_x, m1w, m1b, p_m21, Bsz, 10584, EMB, 0);
    // heads
    k_heads<<<Bsz, 64>>>(otw, otb, ctw, ctb);
    // decoder
    int tot42 = Bsz * DEPTH * 42 * 42;
    k_upsample<<<(tot42 + 255) / 256, 256>>>(p_m21, p_m42a, 21, 42, tot42);
    k_convres<<<dim3(7, Bsz), 128, 54528>>>(p_m42a, c1w, c1b, p_m42b, 42);
    int tot84 = Bsz * DEPTH * 84 * 84;
    k_upsample<<<(tot84 + 255) / 256, 256>>>(p_m42b, p_m84a, 42, 84, tot84);
    k_convres<<<dim3(14, Bsz), 256, 86784>>>(p_m84a, c2w, c2b, p_m84b, 84);
    // fused: 1x1 conv + sigmoid masks + flow + warp
    k_final<<<dim3(28, Bsz), 256>>>(inp, c3w, c3b, outp);
    (void)in_sizes; (void)n_in; (void)out_size;
}

// round 4
// speedup vs baseline: 1.3240x; 1.3240x over previous
#include <cuda_runtime.h>
#include <math.h>

#define Bsz 512
#define HH 84
#define WW 84
#define KOBJ 20
#define DEPTH 24
#define EMB 512

// ---------------- scratch (static device globals; no allocations) ----------------
__device__ float g_h1[Bsz * 32 * 20 * 20];          // conv1 out
__device__ float g_h2[Bsz * 64 * 9 * 9];            // conv2 out
__device__ float g_h3[Bsz * 64 * 7 * 7];            // conv3 out / feat
__device__ float g_fcpart[7 * Bsz * EMB];           // fc split-K partials
__device__ float g_x [Bsz * EMB];                   // fc out
__device__ float g_ot[Bsz * KOBJ * 2];
__device__ float g_ct[Bsz * 2];
__device__ float g_m21 [Bsz * DEPTH * 21 * 21];
__device__ float g_m42b[Bsz * DEPTH * 42 * 42];
__device__ float g_m84b[Bsz * DEPTH * 84 * 84];

// ---------------- conv1: [B,2,84,84] k8 s4 -> [B,32,20,20], relu ----------------
__global__ __launch_bounds__(256) void k_conv1(const float* __restrict__ inp,
                                               const float* __restrict__ w,
                                               const float* __restrict__ bias) {
    extern __shared__ float sm[];
    float* sIn = sm;          // 2*84*84 = 14112
    float* sW  = sm + 14112;  // 32*2*8*8 = 4096
    int b = blockIdx.x, tid = threadIdx.x;
    const float* ip = inp + b * 14112;
    for (int i = tid; i < 14112; i += 256) sIn[i] = ip[i];
    for (int i = tid; i < 4096;  i += 256) sW[i]  = w[i];
    __syncthreads();
    for (int o = tid; o < 3200; o += 256) {
        int oc = o / 100; int r = o % 100;
        int oy = (r / 10) * 2, ox = (r % 10) * 2;
        float a00 = 0.f, a01 = 0.f, a10 = 0.f, a11 = 0.f;
        for (int ic = 0; ic < 2; ic++) {
            const float* wp  = sW + (oc * 2 + ic) * 64;
            const float* inb = sIn + ic * 7056;
            #pragma unroll
            for (int ky = 0; ky < 8; ky++) {
                const float* r0 = inb + (oy * 4 + ky) * 84 + ox * 4;
                const float* r1 = r0 + 4 * 84;
                float v0[12], v1[12];
                #pragma unroll
                for (int j = 0; j < 12; j++) { v0[j] = r0[j]; v1[j] = r1[j]; }
                #pragma unroll
                for (int kx = 0; kx < 8; kx++) {
                    float ww = wp[ky * 8 + kx];
                    a00 += v0[kx] * ww;  a01 += v0[kx + 4] * ww;
                    a10 += v1[kx] * ww;  a11 += v1[kx + 4] * ww;
                }
            }
        }
        float bb = bias[oc];
        float* op = g_h1 + b * 12800 + oc * 400 + oy * 20 + ox;
        op[0]  = fmaxf(a00 + bb, 0.f); op[1]  = fmaxf(a01 + bb, 0.f);
        op[20] = fmaxf(a10 + bb, 0.f); op[21] = fmaxf(a11 + bb, 0.f);
    }
}

// ---------------- conv2: [B,32,20,20] k4 s2 -> [B,64,9,9], relu ----------------
__global__ __launch_bounds__(256) void k_conv2(const float* __restrict__ w,
                                               const float* __restrict__ bias) {
    extern __shared__ float sm[];
    float* sIn = sm;          // 32*20*20 = 12800
    float* sW  = sm + 12800;  // chunk: 32 oc * 32 ic * 16 = 16384
    int b = blockIdx.x, tid = threadIdx.x;
    const float* ip = g_h1 + b * 12800;
    for (int i = tid; i < 12800; i += 256) sIn[i] = ip[i];
    for (int ch = 0; ch < 2; ch++) {
        __syncthreads();
        for (int i = tid; i < 16384; i += 256) sW[i] = w[ch * 16384 + i];
        __syncthreads();
        if (tid < 216) {
            int ocg = tid / 27; int r = tid % 27; int oy = r / 3; int oxg = (r % 3) * 3;
            float acc[4][3] = {};
            int iy0 = oy * 2, ix0 = oxg * 2;
            for (int ic = 0; ic < 32; ic++) {
                #pragma unroll
                for (int ky = 0; ky < 4; ky++) {
                    const float* rp = sIn + ic * 400 + (iy0 + ky) * 20 + ix0;
                    float v[8];
                    #pragma unroll
                    for (int j = 0; j < 8; j++) v[j] = rp[j];
                    #pragma unroll
                    for (int u = 0; u < 4; u++) {
                        const float* wp = sW + ((ocg * 4 + u) * 32 + ic) * 16 + ky * 4;
                        #pragma unroll
                        for (int kx = 0; kx < 4; kx++) {
                            float ww = wp[kx];
                            acc[u][0] += v[kx] * ww;
                            acc[u][1] += v[kx + 2] * ww;
                            acc[u][2] += v[kx + 4] * ww;
                        }
                    }
                }
            }
            #pragma unroll
            for (int u = 0; u < 4; u++) {
                int oc = ch * 32 + ocg * 4 + u;
                float bb = bias[oc];
                float* op = g_h2 + b * 5184 + oc * 81 + oy * 9 + oxg;
                #pragma unroll
                for (int j = 0; j < 3; j++) op[j] = fmaxf(acc[u][j] + bb, 0.f);
            }
        }
    }
}

// ---------------- conv3: [B,64,9,9] k3 s1 -> [B,64,7,7], relu ----------------
__global__ __launch_bounds__(256) void k_conv3(const float* __restrict__ w,
                                               const float* __restrict__ bias) {
    extern __shared__ float sm[];
    float* sIn = sm;         // 64*81 = 5184
    float* sW  = sm + 5184;  // 64*64*9 = 36864
    int b = blockIdx.x, tid = threadIdx.x;
    const float* ip = g_h2 + b * 5184;
    for (int i = tid; i < 5184;  i += 256) sIn[i] = ip[i];
    for (int i = tid; i < 36864; i += 256) sW[i]  = w[i];
    __syncthreads();
    for (int it = tid; it < 448; it += 256) {
        int oc = it / 7, oy = it % 7;
        float acc[7] = {};
        for (int ic = 0; ic < 64; ic++) {
            const float* wp = sW + (oc * 64 + ic) * 9;
            #pragma unroll
            for (int ky = 0; ky < 3; ky++) {
                const float* rp = sIn + ic * 81 + (oy + ky) * 9;
                float v[9];
                #pragma unroll
                for (int j = 0; j < 9; j++) v[j] = rp[j];
                #pragma unroll
                for (int kx = 0; kx < 3; kx++) {
                    float ww = wp[ky * 3 + kx];
                    #pragma unroll
                    for (int j = 0; j < 7; j++) acc[j] += v[j + kx] * ww;
                }
            }
        }
        float bb = bias[oc];
        float* op = g_h3 + b * 3136 + oc * 49 + oy * 7;
        #pragma unroll
        for (int j = 0; j < 7; j++) op[j] = fmaxf(acc[j] + bb, 0.f);
    }
}

// ---------------- GEMM v2: C[M,N] = A[M,K] * W[N,K]^T (+bias, relu optional)
// BM=128, BN=64, BK=16, 256 threads, 8x4 microtile, float4 loads.
// If Kc < K: split-K, block z writes raw partial to C + z*M*N (no bias).
#define GBM 128
#define GBN 64
#define GBK 16
__global__ __launch_bounds__(256) void k_gemm2(const float* __restrict__ A,
                                               const float* __restrict__ W,
                                               const float* __restrict__ bias,
                                               float* __restrict__ C,
                                               int M, int N, int K, int Kc, int relu) {
    __shared__ float As[GBK][GBM];
    __shared__ float Ws[GBK][GBN];
    int bm = blockIdx.y * GBM, bn = blockIdx.x * GBN;
    int ks = blockIdx.z * Kc;
    int ke = min(ks + Kc, K);
    int tid = threadIdx.x;
    float acc[8][4];
    #pragma unroll
    for (int i = 0; i < 8; i++)
        #pragma unroll
        for (int j = 0; j < 4; j++) acc[i][j] = 0.f;

    int tm = (tid / 16) * 8, tn = (tid % 16) * 4;

    for (int k0 = ks; k0 < ke; k0 += GBK) {
        // As: 128x16 (2048 elems = 512 float4), 2 per thread
        #pragma unroll
        for (int l = tid; l < 512; l += 256) {
            int m = l >> 2, kq = (l & 3) << 2;
            float4 v = *(const float4*)(A + (size_t)(bm + m) * K + k0 + kq);
            As[kq + 0][m] = v.x; As[kq + 1][m] = v.y;
            As[kq + 2][m] = v.z; As[kq + 3][m] = v.w;
        }
        // Ws: 64x16 (1024 elems = 256 float4), 1 per thread
        {
            int n = tid >> 2, kq = (tid & 3) << 2;
            int gn = bn + n;
            float4 v = make_float4(0.f, 0.f, 0.f, 0.f);
            if (gn < N) v = *(const float4*)(W + (size_t)gn * K + k0 + kq);
            Ws[kq + 0][n] = v.x; Ws[kq + 1][n] = v.y;
            Ws[kq + 2][n] = v.z; Ws[kq + 3][n] = v.w;
        }
        __syncthreads();
        #pragma unroll
        for (int k = 0; k < GBK; k++) {
            float4 a0 = *(const float4*)&As[k][tm];
            float4 a1 = *(const float4*)&As[k][tm + 4];
            float4 bv = *(const float4*)&Ws[k][tn];
            float a[8] = {a0.x, a0.y, a0.z, a0.w, a1.x, a1.y, a1.z, a1.w};
            float bb[4] = {bv.x, bv.y, bv.z, bv.w};
            #pragma unroll
            for (int i = 0; i < 8; i++)
                #pragma unroll
                for (int j = 0; j < 4; j++) acc[i][j] += a[i] * bb[j];
        }
        __syncthreads();
    }

    if (Kc >= K) {
        #pragma unroll
        for (int i = 0; i < 8; i++) {
            int gm = bm + tm + i;
            #pragma unroll
            for (int j = 0; j < 4; j++) {
                int gn = bn + tn + j;
                if (gn < N) {
                    float v = acc[i][j] + bias[gn];
                    if (relu) v = fmaxf(v, 0.f);
                    C[(size_t)gm * N + gn] = v;
                }
            }
        }
    } else {
        float* Cp = C + (size_t)blockIdx.z * M * N;
        #pragma unroll
        for (int i = 0; i < 8; i++) {
            int gm = bm + tm + i;
            #pragma unroll
            for (int j = 0; j < 4; j++) {
                int gn = bn + tn + j;
                if (gn < N) Cp[(size_t)gm * N + gn] = acc[i][j];
            }
        }
    }
}

// ---------------- fc reduce: sum 7 partials + bias + relu -> g_x ----------------
__global__ __launch_bounds__(256) void k_fcreduce(const float* __restrict__ fcb) {
    int i = blockIdx.x * 256 + threadIdx.x;
    if (i >= Bsz * EMB) return;
    int n = i & (EMB - 1);
    float s = fcb[n];
    #pragma unroll
    for (int p = 0; p < 7; p++) s += g_fcpart[p * Bsz * EMB + i];
    g_x[i] = fmaxf(s, 0.f);
}

// ---------------- heads: ot[B,40], ct[B,2] ----------------
__global__ __launch_bounds__(64) void k_heads(const float* __restrict__ otw,
                                              const float* __restrict__ otb,
                                              const float* __restrict__ ctw,
                                              const float* __restrict__ ctb) {
    __shared__ float sx[EMB];
    int b = blockIdx.x, tid = threadIdx.x;
    for (int i = tid; i < EMB; i += 64) sx[i] = g_x[b * EMB + i];
    __syncthreads();
    if (tid < 42) {
        const float* wp = (tid < 40) ? (otw + tid * EMB) : (ctw + (tid - 40) * EMB);
        float s = (tid < 40) ? otb[tid] : ctb[tid - 40];
        for (int k = 0; k < EMB; k++) s += sx[k] * wp[k];
        if (tid < 40) g_ot[b * 40 + tid] = s;
        else          g_ct[b * 2 + (tid - 40)] = s;
    }
}

// ---------------- fused: bilinear up (inS -> S=2*inS, align_corners) + residual 3x3 conv
// out = relu(up(src) + conv3x3(up(src)) + b).  TH=6 output rows per block.
// Compute mapping: thread -> (ocg of 8, y, xg of 6).
__global__ __launch_bounds__(256) void k_upconvres(const float* __restrict__ src,
                                                   const float* __restrict__ w,
                                                   const float* __restrict__ bias,
                                                   float* __restrict__ out,
                                                   int inS, int S) {
    extern __shared__ float sm[];
    const int TH = 6;
    int Sp = S + 2;
    float* sIn = sm;                       // 24*(TH+2)*Sp
    float* sW  = sm + 24 * (TH + 2) * Sp;  // 5184
    int b = blockIdx.y, ty = blockIdx.x;
    int tid = threadIdx.x;
    int y0 = ty * TH;
    float scale = (float)(inS - 1) / (float)(S - 1);

    // fill smem tile with upsampled values (zero border padding)
    int tileElems = 24 * (TH + 2) * Sp;
    const float* sb = src + (size_t)b * 24 * inS * inS;
    for (int i = tid; i < tileElems; i += 256) {
        int cx = i % Sp; int t = i / Sp; int ry = t % (TH + 2); int c = t / (TH + 2);
        int gy = y0 + ry - 1, gx = cx - 1;
        float v = 0.f;
        if (gy >= 0 && gy < S && gx >= 0 && gx < S) {
            float py = gy * scale, px = gx * scale;
            int yl = min((int)py, inS - 2);
            int xl = min((int)px, inS - 2);
            float wy = py - (float)yl, wx = px - (float)xl;
            const float* sp = sb + ((size_t)c * inS + yl) * inS + xl;
            float v00 = sp[0], v01 = sp[1], v10 = sp[inS], v11 = sp[inS + 1];
            v = (1.f - wy) * ((1.f - wx) * v00 + wx * v01) +
                wy * ((1.f - wx) * v10 + wx * v11);
        }
        sIn[i] = v;
    }
    for (int i = tid; i < 5184; i += 256) sW[i] = w[i];
    __syncthreads();

    int nxg = S / 6;
    int nact = 3 * TH * nxg;
    if (tid >= nact) return;
    int ocg = tid / (TH * nxg);
    int r = tid % (TH * nxg);
    int y = r / nxg;
    int xb = (r % nxg) * 6;

    float acc[8][6];
    #pragma unroll
    for (int u = 0; u < 8; u++)
        #pragma unroll
        for (int j = 0; j < 6; j++) acc[u][j] = 0.f;

    for (int ic = 0; ic < 24; ic++) {
        float vin[3][8];
        #pragma unroll
        for (int ky = 0; ky < 3; ky++) {
            const float* rp = sIn + (ic * (TH + 2) + y + ky) * Sp + xb;
            #pragma unroll
            for (int j = 0; j < 8; j++) vin[ky][j] = rp[j];
        }
        #pragma unroll
        for (int u = 0; u < 8; u++) {
            const float* wp = sW + ((ocg * 8 + u) * 24 + ic) * 9;
            float wr[9];
            #pragma unroll
            for (int q = 0; q < 9; q++) wr[q] = wp[q];
            #pragma unroll
            for (int ky = 0; ky < 3; ky++)
                #pragma unroll
                for (int kx = 0; kx < 3; kx++) {
                    float ww = wr[ky * 3 + kx];
                    #pragma unroll
                    for (int j = 0; j < 6; j++)
                        acc[u][j] += vin[ky][j + kx] * ww;
                }
        }
    }

    int gy = y0 + y;
    float* ob = out + (size_t)b * 24 * S * S;
    #pragma unroll
    for (int u = 0; u < 8; u++) {
        int oc = ocg * 8 + u;
        float bb = bias[oc];
        const float* cp = sIn + (oc * (TH + 2) + y + 1) * Sp + xb + 1;
        float* op = ob + ((size_t)oc * S + gy) * S + xb;
        #pragma unroll
        for (int j = 0; j < 6; j++)
            op[j] = fmaxf(acc[u][j] + cp[j] + bb, 0.f);
    }
}

// ---------------- fused epilogue: 1x1 conv + sigmoid + flow + ct + grid + warp ----------------
__global__ __launch_bounds__(256) void k_final(const float* __restrict__ inp,
                                               const float* __restrict__ c3w,
                                               const float* __restrict__ c3b,
                                               float* __restrict__ outp) {
    __shared__ float s_w[KOBJ * 24];
    __shared__ float s_b[KOBJ];
    __shared__ float s_ot[KOBJ * 2];
    __shared__ float s_ct[2];
    int b = blockIdx.y, tid = threadIdx.x;
    int p = blockIdx.x * 256 + tid;
    for (int i = tid; i < KOBJ * 24; i += 256) s_w[i] = c3w[i];
    if (tid < KOBJ) s_b[tid] = c3b[tid];
    if (tid < KOBJ * 2) s_ot[tid] = g_ot[b * 40 + tid];
    if (tid < 2) s_ct[tid] = g_ct[b * 2 + tid];
    __syncthreads();
    if (p >= 7056) return;
    const float* mp = g_m84b + (size_t)b * 24 * 7056 + p;
    float mv[24];
    #pragma unroll
    for (int c = 0; c < 24; c++) mv[c] = mp[c * 7056];
    float fy = s_ct[0], fx = s_ct[1];
    #pragma unroll 4
    for (int k = 0; k < KOBJ; k++) {
        float s = s_b[k];
        #pragma unroll
        for (int c = 0; c < 24; c++) s += mv[c] * s_w[k * 24 + c];
        float mask = 1.f / (1.f + __expf(-s));
        fy += mask * s_ot[k * 2];
        fx += mask * s_ot[k * 2 + 1];
    }
    int gy = p / 84, gx = p % 84;
    const float isf = 0.01f * 84.0f;
    float ys = isf * fy + (float)gy;
    float xs = isf * fx + (float)gx;
    const float* src = inp + (size_t)b * 14112 + 7056;  // frame 1
    int x0 = min(max((int)floorf(xs), 0), 83);
    int y0 = min(max((int)floorf(ys), 0), 83);
    int x1 = min(x0 + 1, 83);
    int y1 = min(y0 + 1, 83);
    float Ia = src[y0 * 84 + x0], Ib = src[y1 * 84 + x0];
    float Ic = src[y0 * 84 + x1], Id = src[y1 * 84 + x1];
    float xc = fminf(fmaxf(xs, 0.f), 83.f);
    float yc = fminf(fmaxf(ys, 0.f), 83.f);
    float x0f = (float)x0, x1f = (float)x1, y0f = (float)y0, y1f = (float)y1;
    float o = (x1f - xc) * (y1f - yc) * Ia + (x1f - xc) * (yc - y0f) * Ib +
              (xc - x0f) * (y1f - yc) * Ic + (xc - x0f) * (yc - y0f) * Id;
    outp[(size_t)b * 7056 + p] = o;
}

// ---------------- launch ----------------
extern "C" void kernel_launch(void* const* d_in, const int* in_sizes, int n_in,
                              void* d_out, int out_size) {
    const float* inp = (const float*)d_in[0];
    const float* cw1 = (const float*)d_in[1];
    const float* cb1 = (const float*)d_in[2];
    const float* cw2 = (const float*)d_in[3];
    const float* cb2 = (const float*)d_in[4];
    const float* cw3 = (const float*)d_in[5];
    const float* cb3 = (const float*)d_in[6];
    const float* fcw = (const float*)d_in[7];
    const float* fcb = (const float*)d_in[8];
    const float* otw = (const float*)d_in[9];
    const float* otb = (const float*)d_in[10];
    const float* ctw = (const float*)d_in[11];
    const float* ctb = (const float*)d_in[12];
    const float* m1w = (const float*)d_in[13];
    const float* m1b = (const float*)d_in[14];
    const float* c1w = (const float*)d_in[15];
    const float* c1b = (const float*)d_in[16];
    const float* c2w = (const float*)d_in[17];
    const float* c2b = (const float*)d_in[18];
    const float* c3w = (const float*)d_in[19];
    const float* c3b = (const float*)d_in[20];
    float* outp = (float*)d_out;

    // dynamic smem opt-in (>48KB); idempotent, capture-safe
    cudaFuncSetAttribute(k_conv1,  cudaFuncAttributeMaxDynamicSharedMemorySize, 72832);
    cudaFuncSetAttribute(k_conv2,  cudaFuncAttributeMaxDynamicSharedMemorySize, 116736);
    cudaFuncSetAttribute(k_conv3,  cudaFuncAttributeMaxDynamicSharedMemorySize, 168192);
    cudaFuncSetAttribute(k_upconvres, cudaFuncAttributeMaxDynamicSharedMemorySize, 86784);

    float *p_h3, *p_x, *p_fcpart, *p_m21, *p_m42b, *p_m84b;
    cudaGetSymbolAddress((void**)&p_h3,     g_h3);
    cudaGetSymbolAddress((void**)&p_x,      g_x);
    cudaGetSymbolAddress((void**)&p_fcpart, g_fcpart);
    cudaGetSymbolAddress((void**)&p_m21,    g_m21);
    cudaGetSymbolAddress((void**)&p_m42b,   g_m42b);
    cudaGetSymbolAddress((void**)&p_m84b,   g_m84b);

    // encoder
    k_conv1<<<Bsz, 256, 72832>>>(inp, cw1, cb1);
    k_conv2<<<Bsz, 256, 116736>>>(cw2, cb2);
    k_conv3<<<Bsz, 256, 168192>>>(cw3, cb3);
    // fc: [512,3136] x [512,3136]^T -> [512,512], split-K=7 (Kc=448) + reduce(relu)
    k_gemm2<<<dim3(EMB / GBN, Bsz / GBM, 7), 256>>>(p_h3, fcw, fcb, p_fcpart,
                                                    Bsz, EMB, 3136, 448, 0);
    k_fcreduce<<<(Bsz * EMB + 255) / 256, 256>>>(fcb);
    // mask fc: [512,512] x [10584,512]^T -> [512,10584]
    k_gemm2<<<dim3((10584 + GBN - 1) / GBN, Bsz / GBM, 1), 256>>>(p_x, m1w, m1b, p_m21,
                                                                  Bsz, 10584, EMB, EMB, 0);
    // heads
    k_heads<<<Bsz, 64>>>(otw, otb, ctw, ctb);
    // decoder: fused upsample + residual conv
    k_upconvres<<<dim3(7, Bsz), 256, 54528>>>(p_m21, c1w, c1b, p_m42b, 21, 42);
    k_upconvres<<<dim3(14, Bsz), 256, 86784>>>(p_m42b, c2w, c2b, p_m84b, 42, 84);
    // fused: 1x1 conv + sigmoid masks + flow + warp
    k_final<<<dim3(28, Bsz), 256>>>(inp, c3w, c3b, outp);
    (void)in_sizes; (void)n_in; (void)out_size;
}